// round 15
// baseline (speedup 1.0000x reference)
#include <cuda_runtime.h>
#include <cuda_fp16.h>
#include <cuda_bf16.h>
#include <mma.h>

using namespace nvcuda;

#define NN 50000
#define EE 800000
#define FI 128
#define HH 128
#define GG 256
#define TT 4

#define SCAN_BLKS 49   // 12500 int4 / 256

// ---------------- streams/events (created once at program init) ----------------
struct SideStream {
    cudaStream_t s2;
    cudaEvent_t  evFork, evDinv, evCsr;
    SideStream() {
        cudaStreamCreateWithFlags(&s2, cudaStreamNonBlocking);
        cudaEventCreateWithFlags(&evFork, cudaEventDisableTiming);
        cudaEventCreateWithFlags(&evDinv, cudaEventDisableTiming);
        cudaEventCreateWithFlags(&evCsr,  cudaEventDisableTiming);
    }
};
static SideStream g_ss;

// ---------------- scratch (device globals) ----------------
__device__ int    g_deg[NN];
__device__ int    g_rowptr[NN + 1];
__device__ int    g_pos[NN];
__device__ int    g_col[EE];
__device__ float  g_dinv[NN];
__device__ int    g_blk_agg[SCAN_BLKS];
__device__ int    g_blk_pfx[SCAN_BLKS];
__device__ int    g_blk_stat[SCAN_BLKS];   // 0 none, 1 agg ready, 2 prefix ready
__device__ uint2  g_tsh[NN * 32];          // ts = dinv*(X@W) fp16, 4 halves/uint2
__device__ float4 g_h[NN * 32];            // layer activations (fp32)
__device__ __half g_Whi[2][128 * 128];     // W split: hi part (fp16)
__device__ __half g_Wlo[2][128 * 128];     // W split: lo part (fp16)

// ---------------- init: zero deg + scan statuses + rowptr[NN] + split-pack W1/W2 ----------
__global__ void k_init(const float* __restrict__ W1, const float* __restrict__ W2) {
    int idx = blockIdx.x * blockDim.x + threadIdx.x;   // 128 blocks x 256 = 32768
    if (idx < NN / 4) ((int4*)g_deg)[idx] = make_int4(0, 0, 0, 0);
    if (idx < SCAN_BLKS) g_blk_stat[idx] = 0;
    if (idx == 0) g_rowptr[NN] = EE;
    int m = idx >> 14;          // 0: W1, 1: W2
    int e = idx & 16383;        // 0..16383
    const float* W = m ? W2 : W1;
    float w = W[e];
    __half hi = __float2half_rn(w);
    __half lo = __float2half_rn(w - __half2float(hi));
    g_Whi[m][e] = hi;
    g_Wlo[m][e] = lo;
}

// ---------------- degree histogram (edge_index is int32) ----------------
__global__ void k_hist(const int* __restrict__ ei) {
    int e4 = blockIdx.x * blockDim.x + threadIdx.x;
    if (e4 < EE / 4) {
        int4 d = ((const int4*)(ei + EE))[e4];
        atomicAdd(&g_deg[d.x], 1);
        atomicAdd(&g_deg[d.y], 1);
        atomicAdd(&g_deg[d.z], 1);
        atomicAdd(&g_deg[d.w], 1);
    }
}

// ---------------- single-pass scan with decoupled lookback (49 blocks) ----------------
__global__ void k_scan() {
    __shared__ int ws[8];
    __shared__ int sh_off;
    __shared__ int sh_bt;
    int tid = threadIdx.x, lane = tid & 31, wid = tid >> 5;
    int i4 = blockIdx.x * 256 + tid;
    int4 d = make_int4(0, 0, 0, 0);
    if (i4 < NN / 4) d = ((const int4*)g_deg)[i4];
    int tot = d.x + d.y + d.z + d.w;
    int incl = tot;
    #pragma unroll
    for (int o = 1; o < 32; o <<= 1) {
        int t = __shfl_up_sync(0xffffffffu, incl, o);
        if (lane >= o) incl += t;
    }
    if (lane == 31) ws[wid] = incl;
    __syncthreads();
    if (wid == 0) {
        int s = (lane < 8) ? ws[lane] : 0;
        int si = s;
        #pragma unroll
        for (int o = 1; o < 8; o <<= 1) {
            int t = __shfl_up_sync(0xffffffffu, si, o);
            if (lane >= o) si += t;
        }
        if (lane < 8) ws[lane] = si - s;
    }
    __syncthreads();
    int excl_in_blk = ws[wid] + incl - tot;
    if (tid == 255) sh_bt = excl_in_blk + tot;
    __syncthreads();
    int bt = sh_bt;

    if (tid == 0) {
        if (blockIdx.x == 0) {
            g_blk_pfx[0] = bt;
            __threadfence();
            atomicExch(&g_blk_stat[0], 2);
            sh_off = 0;
        } else {
            g_blk_agg[blockIdx.x] = bt;
            __threadfence();
            atomicExch(&g_blk_stat[blockIdx.x], 1);
            volatile int* vagg = (volatile int*)g_blk_agg;
            volatile int* vpfx = (volatile int*)g_blk_pfx;
            int running = 0;
            for (int j = (int)blockIdx.x - 1; j >= 0; ) {
                int s;
                do { s = atomicAdd(&g_blk_stat[j], 0); } while (s == 0);
                if (s == 2) { running += vpfx[j]; break; }
                running += vagg[j];
                j--;
            }
            sh_off = running;
            g_blk_pfx[blockIdx.x] = running + bt;
            __threadfence();
            atomicExch(&g_blk_stat[blockIdx.x], 2);
        }
    }
    __syncthreads();
    int run = sh_off + excl_in_blk;
    if (i4 < NN / 4) {
        int p0 = run, p1 = p0 + d.x, p2 = p1 + d.y, p3 = p2 + d.z;
        ((int4*)g_rowptr)[i4] = make_int4(p0, p1, p2, p3);
        ((int4*)g_pos)[i4]    = make_int4(p0, p1, p2, p3);
        float4 dv;
        dv.x = rsqrtf((float)(d.x + 1));
        dv.y = rsqrtf((float)(d.y + 1));
        dv.z = rsqrtf((float)(d.z + 1));
        dv.w = rsqrtf((float)(d.w + 1));
        ((float4*)g_dinv)[i4] = dv;
    }
}

__global__ void k_fill(const int* __restrict__ ei) {
    int e4 = blockIdx.x * blockDim.x + threadIdx.x;
    if (e4 < EE / 4) {
        int4 d = ((const int4*)(ei + EE))[e4];
        int4 s = ((const int4*)ei)[e4];
        int p;
        p = atomicAdd(&g_pos[d.x], 1); g_col[p] = s.x;
        p = atomicAdd(&g_pos[d.y], 1); g_col[p] = s.y;
        p = atomicAdd(&g_pos[d.z], 1); g_col[p] = s.z;
        p = atomicAdd(&g_pos[d.w], 1); g_col[p] = s.w;
    }
}

// ---------------- tensor-core GEMM (wmma, split-fp16): g_tsh = fp16(dinv * (X @ W)) ------
// block: 64x128 tile, 256 threads (8 warps). warp w: row-tile rt=w>>1 (16 rows),
// col-half ch=w&1 (64 cols = 4 wmma col-tiles). Split X/W into hi+lo fp16;
// acc = x_hi*w_hi + x_hi*w_lo + x_lo*w_hi (fp32 accum) => ~fp32 accuracy.
template <int SEL>
__global__ void k_gemm(const float4* __restrict__ Xin) {
    __shared__ __align__(32) char smem_buf[32768];
    __half* Xs_hi = (__half*)smem_buf;            // 64*128 half = 16KB
    __half* Xs_lo = Xs_hi + 64 * 128;             // 16KB
    float*  stage = (float*)smem_buf;             // overlay: 8 warps * 16*64 floats = 32KB

    const float4* X4 = SEL ? (const float4*)g_h : Xin;
    const __half* Whi = g_Whi[SEL];
    const __half* Wlo = g_Wlo[SEL];

    int tid  = threadIdx.x;
    int row0 = blockIdx.x * 64;

    // load X tile, split into hi/lo fp16
    #pragma unroll
    for (int j = 0; j < 8; j++) {
        int fi = tid + j * 256;       // float4 index 0..2047
        int r  = fi >> 5;             // row 0..63
        int kq = fi & 31;             // k-quad
        int gr = row0 + r;
        float4 v = make_float4(0.f, 0.f, 0.f, 0.f);
        if (gr < NN) v = X4[gr * 32 + kq];
        __half h0 = __float2half_rn(v.x), h1 = __float2half_rn(v.y);
        __half h2 = __float2half_rn(v.z), h3 = __float2half_rn(v.w);
        __half l0 = __float2half_rn(v.x - __half2float(h0));
        __half l1 = __float2half_rn(v.y - __half2float(h1));
        __half l2 = __float2half_rn(v.z - __half2float(h2));
        __half l3 = __float2half_rn(v.w - __half2float(h3));
        int base = r * 128 + kq * 4;
        Xs_hi[base] = h0; Xs_hi[base + 1] = h1; Xs_hi[base + 2] = h2; Xs_hi[base + 3] = h3;
        Xs_lo[base] = l0; Xs_lo[base + 1] = l1; Xs_lo[base + 2] = l2; Xs_lo[base + 3] = l3;
    }
    __syncthreads();

    int w  = tid >> 5;
    int rt = w >> 1;          // row tile 0..3
    int ch = w & 1;           // col half 0..1

    wmma::fragment<wmma::accumulator, 16, 16, 16, float> acc[4];
    #pragma unroll
    for (int c = 0; c < 4; c++) wmma::fill_fragment(acc[c], 0.0f);

    #pragma unroll
    for (int k = 0; k < 8; k++) {
        wmma::fragment<wmma::matrix_a, 16, 16, 16, __half, wmma::row_major> a_hi, a_lo;
        wmma::load_matrix_sync(a_hi, Xs_hi + rt * 16 * 128 + k * 16, 128);
        wmma::load_matrix_sync(a_lo, Xs_lo + rt * 16 * 128 + k * 16, 128);
        #pragma unroll
        for (int c = 0; c < 4; c++) {
            int n0 = ch * 64 + c * 16;
            wmma::fragment<wmma::matrix_b, 16, 16, 16, __half, wmma::row_major> b_hi, b_lo;
            wmma::load_matrix_sync(b_hi, Whi + k * 16 * 128 + n0, 128);
            wmma::load_matrix_sync(b_lo, Wlo + k * 16 * 128 + n0, 128);
            wmma::mma_sync(acc[c], a_hi, b_hi, acc[c]);
            wmma::mma_sync(acc[c], a_hi, b_lo, acc[c]);
            wmma::mma_sync(acc[c], a_lo, b_hi, acc[c]);
        }
    }
    __syncthreads();   // smem reuse: all mma reads of Xs done

    // stage accumulators (16 rows x 64 cols per warp)
    float* st = stage + w * (16 * 64);
    #pragma unroll
    for (int c = 0; c < 4; c++)
        wmma::store_matrix_sync(st + c * 16, acc[c], 64, wmma::mem_row_major);
    __syncwarp();

    // epilogue: scale by dinv[row], pack fp16, write
    int lane = tid & 31;
    #pragma unroll
    for (int j = 0; j < 8; j++) {
        int idx = lane + j * 32;       // 0..255 uint2 within warp region
        int r   = idx >> 4;            // 0..15
        int cq  = idx & 15;            // uint2 col within 64-col half
        int gr  = row0 + rt * 16 + r;
        if (gr < NN) {
            float di = g_dinv[gr];
            float v0 = st[r * 64 + cq * 4]     * di;
            float v1 = st[r * 64 + cq * 4 + 1] * di;
            float v2 = st[r * 64 + cq * 4 + 2] * di;
            float v3 = st[r * 64 + cq * 4 + 3] * di;
            __half2 ha = __floats2half2_rn(v0, v1);
            __half2 hb = __floats2half2_rn(v2, v3);
            uint2 o;
            o.x = *reinterpret_cast<unsigned*>(&ha);
            o.y = *reinterpret_cast<unsigned*>(&hb);
            g_tsh[gr * 32 + ch * 16 + cq] = o;
        }
    }
}

// ---------------- aggregation (one warp per node, R8-proven form) ----------------
__device__ __forceinline__ void acc_h4(float4& acc, uint2 u) {
    __half2 h0 = *reinterpret_cast<__half2*>(&u.x);
    __half2 h1 = *reinterpret_cast<__half2*>(&u.y);
    float2 f0 = __half22float2(h0);
    float2 f1 = __half22float2(h1);
    acc.x += f0.x; acc.y += f0.y; acc.z += f1.x; acc.w += f1.y;
}

__global__ void k_agg(const float4* __restrict__ b4) {
    int gtid = blockIdx.x * blockDim.x + threadIdx.x;
    int node = gtid >> 5;
    int lane = threadIdx.x & 31;
    if (node >= NN) return;
    float4 acc = make_float4(0.f, 0.f, 0.f, 0.f);
    acc_h4(acc, g_tsh[node * 32 + lane]);   // self term (already dinv-scaled)
    int s = g_rowptr[node], e = g_rowptr[node + 1];
    int j = s;
    for (; j + 3 < e; j += 4) {
        int c0 = g_col[j], c1 = g_col[j + 1], c2 = g_col[j + 2], c3 = g_col[j + 3];
        uint2 u0 = g_tsh[c0 * 32 + lane];
        uint2 u1 = g_tsh[c1 * 32 + lane];
        uint2 u2 = g_tsh[c2 * 32 + lane];
        uint2 u3 = g_tsh[c3 * 32 + lane];
        acc_h4(acc, u0); acc_h4(acc, u1); acc_h4(acc, u2); acc_h4(acc, u3);
    }
    for (; j < e; j++) {
        acc_h4(acc, g_tsh[g_col[j] * 32 + lane]);
    }
    float di = g_dinv[node];
    float4 bb = b4[lane];
    float4 o;
    o.x = fmaxf(fmaf(acc.x, di, bb.x), 0.f);
    o.y = fmaxf(fmaf(acc.y, di, bb.y), 0.f);
    o.z = fmaxf(fmaf(acc.z, di, bb.z), 0.f);
    o.w = fmaxf(fmaf(acc.w, di, bb.w), 0.f);
    g_h[node * 32 + lane] = o;
}

// ---------------- fused mean-pool + FC + head ----------------
__device__ __forceinline__ int lb_batch(const int* b, int v) {
    int lo = 0, hi = NN;
    while (lo < hi) {
        int m = (lo + hi) >> 1;
        if (b[m] < v) lo = m + 1; else hi = m;
    }
    return lo;
}

__global__ void k_poolhead(const int* __restrict__ batch,
                           const float* __restrict__ Wfc, const float* __restrict__ bfc,
                           const float* __restrict__ Wh, const float* __restrict__ bh,
                           float* __restrict__ out) {
    int g = blockIdx.x;
    int tid = threadIdx.x;   // 0..127
    __shared__ int s0, s1;
    __shared__ float pr[128];
    __shared__ float zs[128];
    if (tid == 0) {
        s0 = lb_batch(batch, g);
        s1 = lb_batch(batch, g + 1);
    }
    __syncthreads();
    int a = s0, bnd = s1;
    const float* h = (const float*)g_h;
    float acc = 0.f;
    int n = a;
    for (; n + 3 < bnd; n += 4) {
        acc += h[n * 128 + tid] + h[(n + 1) * 128 + tid]
             + h[(n + 2) * 128 + tid] + h[(n + 3) * 128 + tid];
    }
    for (; n < bnd; n++) acc += h[n * 128 + tid];
    float cnt = (float)(bnd - a);
    pr[tid] = acc / fmaxf(cnt, 1.f);
    __syncthreads();
    float z = bfc[tid];
    #pragma unroll 4
    for (int k = 0; k < 128; k++) z = fmaf(pr[k], Wfc[k * 128 + tid], z);
    zs[tid] = fmaxf(z, 0.f);
    __syncthreads();
    if (tid < TT * 2) {
        int t = tid >> 1, c = tid & 1;
        float s = bh[t * 2 + c];
        #pragma unroll 4
        for (int k = 0; k < 128; k++) s = fmaf(zs[k], Wh[t * 256 + k * 2 + c], s);
        out[t * (GG * 2) + g * 2 + c] = s;
    }
}

// ---------------- launch: fork-join (GEMM1 waits on dinv, overlaps fill) ----------------
extern "C" void kernel_launch(void* const* d_in, const int* in_sizes, int n_in,
                              void* d_out, int out_size) {
    const float* x     = (const float*)d_in[0];
    const int*   ei    = (const int*)d_in[1];
    const int*   batch = (const int*)d_in[2];
    const float* W1    = (const float*)d_in[3];
    const float* b1    = (const float*)d_in[4];
    const float* W2    = (const float*)d_in[5];
    const float* b2    = (const float*)d_in[6];
    const float* Wfc   = (const float*)d_in[7];
    const float* bfc   = (const float*)d_in[8];
    const float* Wh    = (const float*)d_in[9];
    const float* bh    = (const float*)d_in[10];
    float* out = (float*)d_out;

    cudaStream_t s2 = g_ss.s2;

    // init (zero deg, statuses, split-pack weights)
    k_init<<<128, 256>>>(W1, W2);

    // fork: CSR pipeline on side stream
    cudaEventRecord(g_ss.evFork, 0);
    cudaStreamWaitEvent(s2, g_ss.evFork, 0);

    k_hist<<<(EE / 4 + 255) / 256, 256, 0, s2>>>(ei);
    k_scan<<<SCAN_BLKS, 256, 0, s2>>>();
    cudaEventRecord(g_ss.evDinv, s2);          // dinv/rowptr ready
    k_fill<<<(EE / 4 + 255) / 256, 256, 0, s2>>>(ei);
    cudaEventRecord(g_ss.evCsr, s2);           // col ready

    int tile_blocks = (NN + 63) / 64;
    int agg_blocks  = (NN * 32 + 255) / 256;

    // main: GEMM1 needs dinv only — overlaps k_fill
    cudaStreamWaitEvent(0, g_ss.evDinv, 0);
    k_gemm<0><<<tile_blocks, 256>>>((const float4*)x);

    // join: aggregation needs col list too
    cudaStreamWaitEvent(0, g_ss.evCsr, 0);
    k_agg<<<agg_blocks, 256>>>((const float4*)b1);
    k_gemm<1><<<tile_blocks, 256>>>((const float4*)x);
    k_agg<<<agg_blocks, 256>>>((const float4*)b2);
    k_poolhead<<<GG, 128>>>(batch, Wfc, bfc, Wh, bh, out);
}

// round 16
// speedup vs baseline: 1.0140x; 1.0140x over previous
#include <cuda_runtime.h>
#include <cuda_fp16.h>
#include <cuda_bf16.h>
#include <mma.h>

using namespace nvcuda;

#define NN 50000
#define EE 800000
#define FI 128
#define HH 128
#define GG 256
#define TT 4

#define SCAN_BLKS 49   // 12500 int4 / 256
#define GEMM_SMEM (96 * 1024)

// ---------------- scratch (device globals) ----------------
__device__ int    g_deg[NN];
__device__ int    g_rowptr[NN + 1];
__device__ int    g_pos[NN];
__device__ int    g_col[EE];
__device__ float  g_dinv[NN];
__device__ int    g_blk_agg[SCAN_BLKS];
__device__ int    g_blk_pfx[SCAN_BLKS];
__device__ int    g_blk_stat[SCAN_BLKS];   // 0 none, 1 agg ready, 2 prefix ready
__device__ uint2  g_tsh[NN * 32];          // ts = dinv*(X@W) fp16, 4 halves/uint2
__device__ float4 g_h[NN * 32];            // layer activations (fp32)
__device__ __half g_Whi[2][128 * 128];     // W split hi (fp16)
__device__ __half g_Wlo[2][128 * 128];     // W split lo (fp16)

// ---------------- tensor-core GEMM (wmma, split-fp16, smem-staged W) ----------------
// block: 64x128 tile, 256 threads (8 warps). warp w: row-tile rt=w>>1, col-half ch=w&1.
// acc = x_hi*w_hi + x_hi*w_lo + x_lo*w_hi (fp32 accum) ~ fp32 accuracy.
template <int SEL>
__global__ void k_gemm(const float4* __restrict__ Xin) {
    extern __shared__ __align__(32) char smem[];
    __half* Ws_hi = (__half*)smem;                  // 32KB: 128x128
    __half* Ws_lo = Ws_hi + 128 * 128;              // 32KB
    __half* Xs_hi = Ws_lo + 128 * 128;              // 16KB: 64x128
    __half* Xs_lo = Xs_hi + 64 * 128;               // 16KB
    float*  stage = (float*)(smem + 64 * 1024);     // overlay X region (32KB)

    const float4* X4 = SEL ? (const float4*)g_h : Xin;
    int tid  = threadIdx.x;
    int row0 = blockIdx.x * 64;

    // stage W hi/lo into smem (uint4 copies; L1-hot after first block per SM)
    {
        const uint4* src_hi = (const uint4*)g_Whi[SEL];
        const uint4* src_lo = (const uint4*)g_Wlo[SEL];
        uint4* dst_hi = (uint4*)Ws_hi;
        uint4* dst_lo = (uint4*)Ws_lo;
        #pragma unroll
        for (int j = 0; j < 8; j++) {
            int i = tid + j * 256;    // 2048 uint4 per matrix
            dst_hi[i] = src_hi[i];
            dst_lo[i] = src_lo[i];
        }
    }

    // load X tile, split into hi/lo fp16
    #pragma unroll
    for (int j = 0; j < 8; j++) {
        int fi = tid + j * 256;       // float4 index 0..2047
        int r  = fi >> 5;
        int kq = fi & 31;
        int gr = row0 + r;
        float4 v = make_float4(0.f, 0.f, 0.f, 0.f);
        if (gr < NN) v = X4[gr * 32 + kq];
        __half h0 = __float2half_rn(v.x), h1 = __float2half_rn(v.y);
        __half h2 = __float2half_rn(v.z), h3 = __float2half_rn(v.w);
        __half l0 = __float2half_rn(v.x - __half2float(h0));
        __half l1 = __float2half_rn(v.y - __half2float(h1));
        __half l2 = __float2half_rn(v.z - __half2float(h2));
        __half l3 = __float2half_rn(v.w - __half2float(h3));
        int base = r * 128 + kq * 4;
        Xs_hi[base] = h0; Xs_hi[base + 1] = h1; Xs_hi[base + 2] = h2; Xs_hi[base + 3] = h3;
        Xs_lo[base] = l0; Xs_lo[base + 1] = l1; Xs_lo[base + 2] = l2; Xs_lo[base + 3] = l3;
    }
    __syncthreads();

    int w  = tid >> 5;
    int rt = w >> 1;          // row tile 0..3
    int ch = w & 1;           // col half 0..1

    wmma::fragment<wmma::accumulator, 16, 16, 16, float> acc[4];
    #pragma unroll
    for (int c = 0; c < 4; c++) wmma::fill_fragment(acc[c], 0.0f);

    #pragma unroll
    for (int k = 0; k < 8; k++) {
        wmma::fragment<wmma::matrix_a, 16, 16, 16, __half, wmma::row_major> a_hi, a_lo;
        wmma::load_matrix_sync(a_hi, Xs_hi + rt * 16 * 128 + k * 16, 128);
        wmma::load_matrix_sync(a_lo, Xs_lo + rt * 16 * 128 + k * 16, 128);
        #pragma unroll
        for (int c = 0; c < 4; c++) {
            int n0 = ch * 64 + c * 16;
            wmma::fragment<wmma::matrix_b, 16, 16, 16, __half, wmma::row_major> b_hi, b_lo;
            wmma::load_matrix_sync(b_hi, Ws_hi + k * 16 * 128 + n0, 128);
            wmma::load_matrix_sync(b_lo, Ws_lo + k * 16 * 128 + n0, 128);
            wmma::mma_sync(acc[c], a_hi, b_hi, acc[c]);
            wmma::mma_sync(acc[c], a_hi, b_lo, acc[c]);
            wmma::mma_sync(acc[c], a_lo, b_hi, acc[c]);
        }
    }
    __syncthreads();   // X smem reads done; stage overlay safe

    float* st = stage + w * (16 * 64);
    #pragma unroll
    for (int c = 0; c < 4; c++)
        wmma::store_matrix_sync(st + c * 16, acc[c], 64, wmma::mem_row_major);
    __syncwarp();

    // epilogue: scale by dinv[row], pack fp16, write
    int lane = tid & 31;
    #pragma unroll
    for (int j = 0; j < 8; j++) {
        int idx = lane + j * 32;       // 0..255 uint2 within warp region
        int r   = idx >> 4;            // 0..15
        int cq  = idx & 15;
        int gr  = row0 + rt * 16 + r;
        if (gr < NN) {
            float di = g_dinv[gr];
            float v0 = st[r * 64 + cq * 4]     * di;
            float v1 = st[r * 64 + cq * 4 + 1] * di;
            float v2 = st[r * 64 + cq * 4 + 2] * di;
            float v3 = st[r * 64 + cq * 4 + 3] * di;
            __half2 ha = __floats2half2_rn(v0, v1);
            __half2 hb = __floats2half2_rn(v2, v3);
            uint2 o;
            o.x = *reinterpret_cast<unsigned*>(&ha);
            o.y = *reinterpret_cast<unsigned*>(&hb);
            g_tsh[gr * 32 + ch * 16 + cq] = o;
        }
    }
}

// ---------------- streams/events/attrs (created once at program init) ----------------
struct Boot {
    cudaStream_t s2;
    cudaEvent_t  evFork, evDinv, evCsr;
    Boot() {
        cudaStreamCreateWithFlags(&s2, cudaStreamNonBlocking);
        cudaEventCreateWithFlags(&evFork, cudaEventDisableTiming);
        cudaEventCreateWithFlags(&evDinv, cudaEventDisableTiming);
        cudaEventCreateWithFlags(&evCsr,  cudaEventDisableTiming);
        cudaFuncSetAttribute(k_gemm<0>, cudaFuncAttributeMaxDynamicSharedMemorySize, GEMM_SMEM);
        cudaFuncSetAttribute(k_gemm<1>, cudaFuncAttributeMaxDynamicSharedMemorySize, GEMM_SMEM);
    }
};
static Boot g_ss;

// ---------------- init: zero deg + scan statuses + rowptr[NN] + split-pack W1/W2 ----------
__global__ void k_init(const float* __restrict__ W1, const float* __restrict__ W2) {
    int idx = blockIdx.x * blockDim.x + threadIdx.x;   // 128 blocks x 256 = 32768
    if (idx < NN / 4) ((int4*)g_deg)[idx] = make_int4(0, 0, 0, 0);
    if (idx < SCAN_BLKS) g_blk_stat[idx] = 0;
    if (idx == 0) g_rowptr[NN] = EE;
    int m = idx >> 14;          // 0: W1, 1: W2
    int e = idx & 16383;
    const float* W = m ? W2 : W1;
    float w = W[e];
    __half hi = __float2half_rn(w);
    __half lo = __float2half_rn(w - __half2float(hi));
    g_Whi[m][e] = hi;
    g_Wlo[m][e] = lo;
}

// ---------------- degree histogram (edge_index is int32) ----------------
__global__ void k_hist(const int* __restrict__ ei) {
    int e4 = blockIdx.x * blockDim.x + threadIdx.x;
    if (e4 < EE / 4) {
        int4 d = ((const int4*)(ei + EE))[e4];
        atomicAdd(&g_deg[d.x], 1);
        atomicAdd(&g_deg[d.y], 1);
        atomicAdd(&g_deg[d.z], 1);
        atomicAdd(&g_deg[d.w], 1);
    }
}

// ---------------- single-pass scan with decoupled lookback (49 blocks) ----------------
__global__ void k_scan() {
    __shared__ int ws[8];
    __shared__ int sh_off;
    __shared__ int sh_bt;
    int tid = threadIdx.x, lane = tid & 31, wid = tid >> 5;
    int i4 = blockIdx.x * 256 + tid;
    int4 d = make_int4(0, 0, 0, 0);
    if (i4 < NN / 4) d = ((const int4*)g_deg)[i4];
    int tot = d.x + d.y + d.z + d.w;
    int incl = tot;
    #pragma unroll
    for (int o = 1; o < 32; o <<= 1) {
        int t = __shfl_up_sync(0xffffffffu, incl, o);
        if (lane >= o) incl += t;
    }
    if (lane == 31) ws[wid] = incl;
    __syncthreads();
    if (wid == 0) {
        int s = (lane < 8) ? ws[lane] : 0;
        int si = s;
        #pragma unroll
        for (int o = 1; o < 8; o <<= 1) {
            int t = __shfl_up_sync(0xffffffffu, si, o);
            if (lane >= o) si += t;
        }
        if (lane < 8) ws[lane] = si - s;
    }
    __syncthreads();
    int excl_in_blk = ws[wid] + incl - tot;
    if (tid == 255) sh_bt = excl_in_blk + tot;
    __syncthreads();
    int bt = sh_bt;

    if (tid == 0) {
        if (blockIdx.x == 0) {
            g_blk_pfx[0] = bt;
            __threadfence();
            atomicExch(&g_blk_stat[0], 2);
            sh_off = 0;
        } else {
            g_blk_agg[blockIdx.x] = bt;
            __threadfence();
            atomicExch(&g_blk_stat[blockIdx.x], 1);
            volatile int* vagg = (volatile int*)g_blk_agg;
            volatile int* vpfx = (volatile int*)g_blk_pfx;
            int running = 0;
            for (int j = (int)blockIdx.x - 1; j >= 0; ) {
                int s;
                do { s = atomicAdd(&g_blk_stat[j], 0); } while (s == 0);
                if (s == 2) { running += vpfx[j]; break; }
                running += vagg[j];
                j--;
            }
            sh_off = running;
            g_blk_pfx[blockIdx.x] = running + bt;
            __threadfence();
            atomicExch(&g_blk_stat[blockIdx.x], 2);
        }
    }
    __syncthreads();
    int run = sh_off + excl_in_blk;
    if (i4 < NN / 4) {
        int p0 = run, p1 = p0 + d.x, p2 = p1 + d.y, p3 = p2 + d.z;
        ((int4*)g_rowptr)[i4] = make_int4(p0, p1, p2, p3);
        ((int4*)g_pos)[i4]    = make_int4(p0, p1, p2, p3);
        float4 dv;
        dv.x = rsqrtf((float)(d.x + 1));
        dv.y = rsqrtf((float)(d.y + 1));
        dv.z = rsqrtf((float)(d.z + 1));
        dv.w = rsqrtf((float)(d.w + 1));
        ((float4*)g_dinv)[i4] = dv;
    }
}

__global__ void k_fill(const int* __restrict__ ei) {
    int e4 = blockIdx.x * blockDim.x + threadIdx.x;
    if (e4 < EE / 4) {
        int4 d = ((const int4*)(ei + EE))[e4];
        int4 s = ((const int4*)ei)[e4];
        // issue all 4 atomics first (independent) -> 4x MLP on the return latency
        int p0 = atomicAdd(&g_pos[d.x], 1);
        int p1 = atomicAdd(&g_pos[d.y], 1);
        int p2 = atomicAdd(&g_pos[d.z], 1);
        int p3 = atomicAdd(&g_pos[d.w], 1);
        g_col[p0] = s.x;
        g_col[p1] = s.y;
        g_col[p2] = s.z;
        g_col[p3] = s.w;
    }
}

// ---------------- aggregation (one warp per node, proven form) ----------------
__device__ __forceinline__ void acc_h4(float4& acc, uint2 u) {
    __half2 h0 = *reinterpret_cast<__half2*>(&u.x);
    __half2 h1 = *reinterpret_cast<__half2*>(&u.y);
    float2 f0 = __half22float2(h0);
    float2 f1 = __half22float2(h1);
    acc.x += f0.x; acc.y += f0.y; acc.z += f1.x; acc.w += f1.y;
}

__global__ void k_agg(const float4* __restrict__ b4) {
    int gtid = blockIdx.x * blockDim.x + threadIdx.x;
    int node = gtid >> 5;
    int lane = threadIdx.x & 31;
    if (node >= NN) return;
    float4 acc = make_float4(0.f, 0.f, 0.f, 0.f);
    acc_h4(acc, g_tsh[node * 32 + lane]);   // self term (already dinv-scaled)
    int s = g_rowptr[node], e = g_rowptr[node + 1];
    int j = s;
    for (; j + 3 < e; j += 4) {
        int c0 = g_col[j], c1 = g_col[j + 1], c2 = g_col[j + 2], c3 = g_col[j + 3];
        uint2 u0 = g_tsh[c0 * 32 + lane];
        uint2 u1 = g_tsh[c1 * 32 + lane];
        uint2 u2 = g_tsh[c2 * 32 + lane];
        uint2 u3 = g_tsh[c3 * 32 + lane];
        acc_h4(acc, u0); acc_h4(acc, u1); acc_h4(acc, u2); acc_h4(acc, u3);
    }
    for (; j < e; j++) {
        acc_h4(acc, g_tsh[g_col[j] * 32 + lane]);
    }
    float di = g_dinv[node];
    float4 bb = b4[lane];
    float4 o;
    o.x = fmaxf(fmaf(acc.x, di, bb.x), 0.f);
    o.y = fmaxf(fmaf(acc.y, di, bb.y), 0.f);
    o.z = fmaxf(fmaf(acc.z, di, bb.z), 0.f);
    o.w = fmaxf(fmaf(acc.w, di, bb.w), 0.f);
    g_h[node * 32 + lane] = o;
}

// ---------------- fused mean-pool + FC + head ----------------
__device__ __forceinline__ int lb_batch(const int* b, int v) {
    int lo = 0, hi = NN;
    while (lo < hi) {
        int m = (lo + hi) >> 1;
        if (b[m] < v) lo = m + 1; else hi = m;
    }
    return lo;
}

__global__ void k_poolhead(const int* __restrict__ batch,
                           const float* __restrict__ Wfc, const float* __restrict__ bfc,
                           const float* __restrict__ Wh, const float* __restrict__ bh,
                           float* __restrict__ out) {
    int g = blockIdx.x;
    int tid = threadIdx.x;   // 0..127
    __shared__ int s0, s1;
    __shared__ float pr[128];
    __shared__ float zs[128];
    if (tid == 0) {
        s0 = lb_batch(batch, g);
        s1 = lb_batch(batch, g + 1);
    }
    __syncthreads();
    int a = s0, bnd = s1;
    const float* h = (const float*)g_h;
    float acc = 0.f;
    int n = a;
    for (; n + 3 < bnd; n += 4) {
        acc += h[n * 128 + tid] + h[(n + 1) * 128 + tid]
             + h[(n + 2) * 128 + tid] + h[(n + 3) * 128 + tid];
    }
    for (; n < bnd; n++) acc += h[n * 128 + tid];
    float cnt = (float)(bnd - a);
    pr[tid] = acc / fmaxf(cnt, 1.f);
    __syncthreads();
    float z = bfc[tid];
    #pragma unroll 4
    for (int k = 0; k < 128; k++) z = fmaf(pr[k], Wfc[k * 128 + tid], z);
    zs[tid] = fmaxf(z, 0.f);
    __syncthreads();
    if (tid < TT * 2) {
        int t = tid >> 1, c = tid & 1;
        float s = bh[t * 2 + c];
        #pragma unroll 4
        for (int k = 0; k < 128; k++) s = fmaf(zs[k], Wh[t * 256 + k * 2 + c], s);
        out[t * (GG * 2) + g * 2 + c] = s;
    }
}

// ---------------- launch: fork-join (GEMM1 waits on dinv, overlaps fill) ----------------
extern "C" void kernel_launch(void* const* d_in, const int* in_sizes, int n_in,
                              void* d_out, int out_size) {
    const float* x     = (const float*)d_in[0];
    const int*   ei    = (const int*)d_in[1];
    const int*   batch = (const int*)d_in[2];
    const float* W1    = (const float*)d_in[3];
    const float* b1    = (const float*)d_in[4];
    const float* W2    = (const float*)d_in[5];
    const float* b2    = (const float*)d_in[6];
    const float* Wfc   = (const float*)d_in[7];
    const float* bfc   = (const float*)d_in[8];
    const float* Wh    = (const float*)d_in[9];
    const float* bh    = (const float*)d_in[10];
    float* out = (float*)d_out;

    cudaStream_t s2 = g_ss.s2;

    // init (zero deg, statuses, split-pack weights)
    k_init<<<128, 256>>>(W1, W2);

    // fork: CSR pipeline on side stream
    cudaEventRecord(g_ss.evFork, 0);
    cudaStreamWaitEvent(s2, g_ss.evFork, 0);

    k_hist<<<(EE / 4 + 255) / 256, 256, 0, s2>>>(ei);
    k_scan<<<SCAN_BLKS, 256, 0, s2>>>();
    cudaEventRecord(g_ss.evDinv, s2);          // dinv/rowptr ready
    k_fill<<<(EE / 4 + 255) / 256, 256, 0, s2>>>(ei);
    cudaEventRecord(g_ss.evCsr, s2);           // col ready

    int tile_blocks = (NN + 63) / 64;
    int agg_blocks  = (NN * 32 + 255) / 256;

    // main: GEMM1 needs dinv only — overlaps k_fill
    cudaStreamWaitEvent(0, g_ss.evDinv, 0);
    k_gemm<0><<<tile_blocks, 256, GEMM_SMEM>>>((const float4*)x);

    // join: aggregation needs col list too
    cudaStreamWaitEvent(0, g_ss.evCsr, 0);
    k_agg<<<agg_blocks, 256>>>((const float4*)b1);
    k_gemm<1><<<tile_blocks, 256, GEMM_SMEM>>>((const float4*)x);
    k_agg<<<agg_blocks, 256>>>((const float4*)b2);
    k_poolhead<<<GG, 128>>>(batch, Wfc, bfc, Wh, bh, out);
}

// round 17
// speedup vs baseline: 1.2987x; 1.2808x over previous
#include <cuda_runtime.h>
#include <cuda_fp16.h>
#include <cuda_bf16.h>

#define NN 50000
#define EE 800000
#define FI 128
#define HH 128
#define GG 256
#define TT 4

#define SCAN_BLKS 49       // 12500 int4 / 256
#define NH 25024           // split point (391 * 64)

// ---------------- streams/events (created once at program init) ----------------
struct Boot {
    cudaStream_t s2;
    cudaEvent_t  evFork, evDinv, evCsr, evAggLo, evAggHi;
    Boot() {
        cudaStreamCreateWithFlags(&s2, cudaStreamNonBlocking);
        cudaEventCreateWithFlags(&evFork,  cudaEventDisableTiming);
        cudaEventCreateWithFlags(&evDinv,  cudaEventDisableTiming);
        cudaEventCreateWithFlags(&evCsr,   cudaEventDisableTiming);
        cudaEventCreateWithFlags(&evAggLo, cudaEventDisableTiming);
        cudaEventCreateWithFlags(&evAggHi, cudaEventDisableTiming);
    }
};
static Boot g_ss;

// ---------------- scratch (device globals) ----------------
__device__ int    g_deg[NN];
__device__ int    g_rowptr[NN + 1];
__device__ int    g_pos[NN];
__device__ int    g_col[EE];
__device__ float  g_dinv[NN];
__device__ int    g_blk_agg[SCAN_BLKS];
__device__ int    g_blk_pfx[SCAN_BLKS];
__device__ int    g_blk_stat[SCAN_BLKS];   // 0 none, 1 agg ready, 2 prefix ready
__device__ uint2  g_tsA[NN * 32];          // layer-1 ts = dinv*(X@W1), fp16
__device__ uint2  g_tsB[NN * 32];          // layer-2 ts = dinv*(h1@W2), fp16
__device__ uint2  g_hh[NN * 32];           // activations h (fp16, packed half2 x2)
__device__ unsigned long long g_Wp1[64 * 128];  // W packed as (W[2t][c], W[2t+1][c]) f32 pairs
__device__ unsigned long long g_Wp2[64 * 128];

__device__ __forceinline__ void ffma2(unsigned long long& d, unsigned long long a,
                                      unsigned long long b) {
    asm("fma.rn.f32x2 %0, %1, %2, %0;" : "+l"(d) : "l"(a), "l"(b));
}

// ---------------- init: zero deg + scan statuses + rowptr[NN] + pack W1/W2 ----------------
__global__ void k_init(const float* __restrict__ W1, const float* __restrict__ W2) {
    int idx = blockIdx.x * blockDim.x + threadIdx.x;   // 64 blocks x 256 = 16384
    if (idx < NN / 4) ((int4*)g_deg)[idx] = make_int4(0, 0, 0, 0);
    if (idx < SCAN_BLKS) g_blk_stat[idx] = 0;
    if (idx == 0) g_rowptr[NN] = EE;
    int half = idx >> 13;
    int j = idx & 8191;
    int t = j >> 7;
    int c = j & 127;
    const float* W = half ? W2 : W1;
    unsigned lo = __float_as_uint(W[(2 * t) * 128 + c]);
    unsigned hi = __float_as_uint(W[(2 * t + 1) * 128 + c]);
    unsigned long long v = ((unsigned long long)hi << 32) | lo;
    if (half) g_Wp2[j] = v; else g_Wp1[j] = v;
}

// ---------------- degree histogram (edge_index is int32) ----------------
__global__ void k_hist(const int* __restrict__ ei) {
    int e4 = blockIdx.x * blockDim.x + threadIdx.x;
    if (e4 < EE / 4) {
        int4 d = ((const int4*)(ei + EE))[e4];
        atomicAdd(&g_deg[d.x], 1);
        atomicAdd(&g_deg[d.y], 1);
        atomicAdd(&g_deg[d.z], 1);
        atomicAdd(&g_deg[d.w], 1);
    }
}

// ---------------- single-pass scan with decoupled lookback (49 blocks) ----------------
__global__ void k_scan() {
    __shared__ int ws[8];
    __shared__ int sh_off;
    __shared__ int sh_bt;
    int tid = threadIdx.x, lane = tid & 31, wid = tid >> 5;
    int i4 = blockIdx.x * 256 + tid;
    int4 d = make_int4(0, 0, 0, 0);
    if (i4 < NN / 4) d = ((const int4*)g_deg)[i4];
    int tot = d.x + d.y + d.z + d.w;
    int incl = tot;
    #pragma unroll
    for (int o = 1; o < 32; o <<= 1) {
        int t = __shfl_up_sync(0xffffffffu, incl, o);
        if (lane >= o) incl += t;
    }
    if (lane == 31) ws[wid] = incl;
    __syncthreads();
    if (wid == 0) {
        int s = (lane < 8) ? ws[lane] : 0;
        int si = s;
        #pragma unroll
        for (int o = 1; o < 8; o <<= 1) {
            int t = __shfl_up_sync(0xffffffffu, si, o);
            if (lane >= o) si += t;
        }
        if (lane < 8) ws[lane] = si - s;
    }
    __syncthreads();
    int excl_in_blk = ws[wid] + incl - tot;
    if (tid == 255) sh_bt = excl_in_blk + tot;
    __syncthreads();
    int bt = sh_bt;

    if (tid == 0) {
        if (blockIdx.x == 0) {
            g_blk_pfx[0] = bt;
            __threadfence();
            atomicExch(&g_blk_stat[0], 2);
            sh_off = 0;
        } else {
            g_blk_agg[blockIdx.x] = bt;
            __threadfence();
            atomicExch(&g_blk_stat[blockIdx.x], 1);
            volatile int* vagg = (volatile int*)g_blk_agg;
            volatile int* vpfx = (volatile int*)g_blk_pfx;
            int running = 0;
            for (int j = (int)blockIdx.x - 1; j >= 0; ) {
                int s;
                do { s = atomicAdd(&g_blk_stat[j], 0); } while (s == 0);
                if (s == 2) { running += vpfx[j]; break; }
                running += vagg[j];
                j--;
            }
            sh_off = running;
            g_blk_pfx[blockIdx.x] = running + bt;
            __threadfence();
            atomicExch(&g_blk_stat[blockIdx.x], 2);
        }
    }
    __syncthreads();
    int run = sh_off + excl_in_blk;
    if (i4 < NN / 4) {
        int p0 = run, p1 = p0 + d.x, p2 = p1 + d.y, p3 = p2 + d.z;
        ((int4*)g_rowptr)[i4] = make_int4(p0, p1, p2, p3);
        ((int4*)g_pos)[i4]    = make_int4(p0, p1, p2, p3);
        float4 dv;
        dv.x = rsqrtf((float)(d.x + 1));
        dv.y = rsqrtf((float)(d.y + 1));
        dv.z = rsqrtf((float)(d.z + 1));
        dv.w = rsqrtf((float)(d.w + 1));
        ((float4*)g_dinv)[i4] = dv;
    }
}

__global__ void k_fill(const int* __restrict__ ei) {
    int e4 = blockIdx.x * blockDim.x + threadIdx.x;
    if (e4 < EE / 4) {
        int4 d = ((const int4*)(ei + EE))[e4];
        int4 s = ((const int4*)ei)[e4];
        int p0 = atomicAdd(&g_pos[d.x], 1);
        int p1 = atomicAdd(&g_pos[d.y], 1);
        int p2 = atomicAdd(&g_pos[d.z], 1);
        int p3 = atomicAdd(&g_pos[d.w], 1);
        g_col[p0] = s.x;
        g_col[p1] = s.y;
        g_col[p2] = s.z;
        g_col[p3] = s.w;
    }
}

// ---------------- GEMM (FFMA2): ts = fp16( dinv[i] * (X[i,:] @ W) ) ----------------
// SEL=0: X = external fp32 x, W1, out g_tsA. SEL=1: X = g_hh (fp16), W2, out g_tsB.
// rowbase allows split launches.
template <int SEL>
__global__ void k_gemm(const float4* __restrict__ Xin, int rowbase) {
    __shared__ float4 Xs4[64 * 32];
    const ulonglong2* Wp2 = (const ulonglong2*)(SEL ? g_Wp2 : g_Wp1);
    int tid  = threadIdx.x;
    int row0 = rowbase + blockIdx.x * 64;

    #pragma unroll
    for (int j = 0; j < 8; j++) {
        int fi = tid + j * 256;
        int r  = fi >> 5;
        int kq = fi & 31;
        int gr = row0 + r;
        float4 v = make_float4(0.f, 0.f, 0.f, 0.f);
        if (gr < NN) {
            if (SEL) {
                uint2 u = g_hh[gr * 32 + kq];
                __half2 h0 = *reinterpret_cast<__half2*>(&u.x);
                __half2 h1 = *reinterpret_cast<__half2*>(&u.y);
                float2 f0 = __half22float2(h0);
                float2 f1 = __half22float2(h1);
                v = make_float4(f0.x, f0.y, f1.x, f1.y);
            } else {
                v = Xin[gr * 32 + kq];
            }
        }
        Xs4[fi] = v;
    }
    __syncthreads();

    int tx = tid & 31;
    int ty = tid >> 5;
    unsigned long long acc2[8][4];
    #pragma unroll
    for (int i = 0; i < 8; i++)
        #pragma unroll
        for (int c = 0; c < 4; c++) acc2[i][c] = 0ull;

    const unsigned long long* Xs64 = (const unsigned long long*)Xs4;
    #pragma unroll 4
    for (int t = 0; t < 64; t++) {
        ulonglong2 wa = Wp2[t * 64 + 2 * tx];
        ulonglong2 wb = Wp2[t * 64 + 2 * tx + 1];
        #pragma unroll
        for (int i = 0; i < 8; i++) {
            unsigned long long xp = Xs64[(ty * 8 + i) * 64 + t];
            ffma2(acc2[i][0], xp, wa.x);
            ffma2(acc2[i][1], xp, wa.y);
            ffma2(acc2[i][2], xp, wb.x);
            ffma2(acc2[i][3], xp, wb.y);
        }
    }

    uint2* ts = SEL ? g_tsB : g_tsA;
    #pragma unroll
    for (int i = 0; i < 8; i++) {
        int gr = row0 + ty * 8 + i;
        if (gr < NN) {
            float di = g_dinv[gr];
            float r[4];
            #pragma unroll
            for (int c = 0; c < 4; c++) {
                unsigned long long v = acc2[i][c];
                r[c] = (__uint_as_float((unsigned)v) + __uint_as_float((unsigned)(v >> 32))) * di;
            }
            __half2 ha = __floats2half2_rn(r[0], r[1]);
            __half2 hb = __floats2half2_rn(r[2], r[3]);
            uint2 o;
            o.x = *reinterpret_cast<unsigned*>(&ha);
            o.y = *reinterpret_cast<unsigned*>(&hb);
            ts[gr * 32 + tx] = o;
        }
    }
}

// ---------------- aggregation (one warp per node): h = relu(dinv*Σ + b), fp16 out ----------
__device__ __forceinline__ void acc_h4(float4& acc, uint2 u) {
    __half2 h0 = *reinterpret_cast<__half2*>(&u.x);
    __half2 h1 = *reinterpret_cast<__half2*>(&u.y);
    float2 f0 = __half22float2(h0);
    float2 f1 = __half22float2(h1);
    acc.x += f0.x; acc.y += f0.y; acc.z += f1.x; acc.w += f1.y;
}

template <int LAYER>
__global__ void k_agg(const float4* __restrict__ b4, int node0, int nodeN) {
    int gtid = blockIdx.x * blockDim.x + threadIdx.x;
    int node = node0 + (gtid >> 5);
    int lane = threadIdx.x & 31;
    if (node >= nodeN) return;
    const uint2* ts = LAYER ? g_tsB : g_tsA;
    float4 acc = make_float4(0.f, 0.f, 0.f, 0.f);
    acc_h4(acc, ts[node * 32 + lane]);   // self term (already dinv-scaled)
    int s = g_rowptr[node], e = g_rowptr[node + 1];
    int j = s;
    for (; j + 3 < e; j += 4) {
        int c0 = g_col[j], c1 = g_col[j + 1], c2 = g_col[j + 2], c3 = g_col[j + 3];
        uint2 u0 = ts[c0 * 32 + lane];
        uint2 u1 = ts[c1 * 32 + lane];
        uint2 u2 = ts[c2 * 32 + lane];
        uint2 u3 = ts[c3 * 32 + lane];
        acc_h4(acc, u0); acc_h4(acc, u1); acc_h4(acc, u2); acc_h4(acc, u3);
    }
    for (; j < e; j++) {
        acc_h4(acc, ts[g_col[j] * 32 + lane]);
    }
    float di = g_dinv[node];
    float4 bb = b4[lane];
    float v0 = fmaxf(fmaf(acc.x, di, bb.x), 0.f);
    float v1 = fmaxf(fmaf(acc.y, di, bb.y), 0.f);
    float v2 = fmaxf(fmaf(acc.z, di, bb.z), 0.f);
    float v3 = fmaxf(fmaf(acc.w, di, bb.w), 0.f);
    __half2 ha = __floats2half2_rn(v0, v1);
    __half2 hb = __floats2half2_rn(v2, v3);
    uint2 o;
    o.x = *reinterpret_cast<unsigned*>(&ha);
    o.y = *reinterpret_cast<unsigned*>(&hb);
    g_hh[node * 32 + lane] = o;
}

// ---------------- fused mean-pool + FC + head (h in fp16) ----------------
__device__ __forceinline__ int lb_batch(const int* b, int v) {
    int lo = 0, hi = NN;
    while (lo < hi) {
        int m = (lo + hi) >> 1;
        if (b[m] < v) lo = m + 1; else hi = m;
    }
    return lo;
}

__global__ void k_poolhead(const int* __restrict__ batch,
                           const float* __restrict__ Wfc, const float* __restrict__ bfc,
                           const float* __restrict__ Wh, const float* __restrict__ bh,
                           float* __restrict__ out) {
    int g = blockIdx.x;
    int tid = threadIdx.x;   // 0..127
    __shared__ int s0, s1;
    __shared__ float pr[128];
    __shared__ float zs[128];
    if (tid == 0) {
        s0 = lb_batch(batch, g);
        s1 = lb_batch(batch, g + 1);
    }
    __syncthreads();
    int a = s0, bnd = s1;
    const __half* h16 = (const __half*)g_hh;
    float acc = 0.f;
    int n = a;
    for (; n + 3 < bnd; n += 4) {
        acc += __half2float(h16[n * 128 + tid])
             + __half2float(h16[(n + 1) * 128 + tid])
             + __half2float(h16[(n + 2) * 128 + tid])
             + __half2float(h16[(n + 3) * 128 + tid]);
    }
    for (; n < bnd; n++) acc += __half2float(h16[n * 128 + tid]);
    float cnt = (float)(bnd - a);
    pr[tid] = acc / fmaxf(cnt, 1.f);
    __syncthreads();
    float z = bfc[tid];
    #pragma unroll 4
    for (int k = 0; k < 128; k++) z = fmaf(pr[k], Wfc[k * 128 + tid], z);
    zs[tid] = fmaxf(z, 0.f);
    __syncthreads();
    if (tid < TT * 2) {
        int t = tid >> 1, c = tid & 1;
        float s = bh[t * 2 + c];
        #pragma unroll 4
        for (int k = 0; k < 128; k++) s = fmaf(zs[k], Wh[t * 256 + k * 2 + c], s);
        out[t * (GG * 2) + g * 2 + c] = s;
    }
}

// ---------------- launch: fork-join + staggered layer-2 pipeline ----------------
extern "C" void kernel_launch(void* const* d_in, const int* in_sizes, int n_in,
                              void* d_out, int out_size) {
    const float* x     = (const float*)d_in[0];
    const int*   ei    = (const int*)d_in[1];
    const int*   batch = (const int*)d_in[2];
    const float* W1    = (const float*)d_in[3];
    const float* b1    = (const float*)d_in[4];
    const float* W2    = (const float*)d_in[5];
    const float* b2    = (const float*)d_in[6];
    const float* Wfc   = (const float*)d_in[7];
    const float* bfc   = (const float*)d_in[8];
    const float* Wh    = (const float*)d_in[9];
    const float* bh    = (const float*)d_in[10];
    float* out = (float*)d_out;

    cudaStream_t s2 = g_ss.s2;

    // init (zero deg, statuses, pack weights)
    k_init<<<64, 256>>>(W1, W2);

    // fork: CSR pipeline on side stream
    cudaEventRecord(g_ss.evFork, 0);
    cudaStreamWaitEvent(s2, g_ss.evFork, 0);

    k_hist<<<(EE / 4 + 255) / 256, 256, 0, s2>>>(ei);
    k_scan<<<SCAN_BLKS, 256, 0, s2>>>();
    cudaEventRecord(g_ss.evDinv, s2);          // dinv/rowptr ready
    k_fill<<<(EE / 4 + 255) / 256, 256, 0, s2>>>(ei);
    cudaEventRecord(g_ss.evCsr, s2);           // col ready

    // main: GEMM1 (full) needs dinv only — overlaps k_fill
    cudaStreamWaitEvent(0, g_ss.evDinv, 0);
    k_gemm<0><<<(NN + 63) / 64, 256>>>((const float4*)x, 0);

    // join: aggregation needs the col list too
    cudaStreamWaitEvent(0, g_ss.evCsr, 0);

    // --- staggered layer-1 agg / layer-2 gemm pipeline ---
    int aggLo_blocks = (NH * 32) / 256;                       // nodes [0, NH)
    int aggHi_blocks = ((NN - NH) * 32 + 255) / 256;          // nodes [NH, NN)
    int gemLo_blocks = NH / 64;                               // rows [0, NH)
    int gemHi_blocks = (NN - NH + 63) / 64;                   // rows [NH, NN)

    k_agg<0><<<aggLo_blocks, 256>>>((const float4*)b1, 0, NH);
    cudaEventRecord(g_ss.evAggLo, 0);

    // side stream: agg1_hi runs concurrently with GEMM2_lo (different pipes)
    cudaStreamWaitEvent(s2, g_ss.evAggLo, 0);
    k_agg<0><<<aggHi_blocks, 256, 0, s2>>>((const float4*)b1, NH, NN);
    cudaEventRecord(g_ss.evAggHi, s2);

    k_gemm<1><<<gemLo_blocks, 256>>>((const float4*)x, 0);

    cudaStreamWaitEvent(0, g_ss.evAggHi, 0);
    k_gemm<1><<<gemHi_blocks, 256>>>((const float4*)x, NH);

    // layer-2 aggregation (full) + pool/head
    k_agg<1><<<(NN * 32 + 255) / 256, 256>>>((const float4*)b2, 0, NN);
    k_poolhead<<<GG, 128>>>(batch, Wfc, bfc, Wh, bh, out);
}